// round 5
// baseline (speedup 1.0000x reference)
#include <cuda_runtime.h>
#include <math.h>
#include <stdint.h>

// ---------------- problem constants ----------------
#define N_NODES 8000
#define NBATCH  8
#define NPROT   1000
#define NE      512000
#define DDIM    200

// ---------------- device scratch ----------------
__device__ float g_cat [N_NODES * 400];   // leaky([px | pm]) concat
__device__ float g_t   [N_NODES * 256];   // leaky(PMF @ mp_W1 + b1)
__device__ float g_px2 [N_NODES * DDIM];
__device__ float g_h   [N_NODES * DDIM];
__device__ float g_a1  [N_NODES * DDIM];
__device__ float g_a2  [N_NODES * DDIM];
__device__ float g_d   [NBATCH * DDIM];
__device__ float g_dinv[N_NODES];
__device__ int   g_cnt [N_NODES];
__device__ int   g_rowstart[N_NODES + 1];
__device__ int   g_cursor[N_NODES];
__device__ int   g_csrc[NE];

__device__ __forceinline__ float leakyf(float x) { return x > 0.0f ? x : 0.2f * x; }

__device__ __forceinline__ uint32_t smem_u32(const void* p) {
    uint32_t a;
    asm("{ .reg .u64 t; cvta.to.shared.u64 t, %1; cvt.u32.u64 %0, t; }" : "=r"(a) : "l"(p));
    return a;
}

__device__ __forceinline__ void cp_async16(uint32_t dst, const void* src, int src_bytes) {
    asm volatile("cp.async.cg.shared.global [%0], [%1], 16, %2;"
                 :: "r"(dst), "l"(src), "r"(src_bytes) : "memory");
}
#define CP_COMMIT() asm volatile("cp.async.commit_group;" ::: "memory")
#define CP_WAIT(n)  asm volatile("cp.async.wait_group %0;" :: "n"(n) : "memory")

__device__ __forceinline__ void mma_tf32(float c[4], const uint32_t a[4], const uint32_t b[2]) {
    asm volatile(
        "mma.sync.aligned.m16n8k8.row.col.f32.tf32.tf32.f32 "
        "{%0,%1,%2,%3}, {%4,%5,%6,%7}, {%8,%9}, {%0,%1,%2,%3};"
        : "+f"(c[0]), "+f"(c[1]), "+f"(c[2]), "+f"(c[3])
        : "r"(a[0]), "r"(a[1]), "r"(a[2]), "r"(a[3]), "r"(b[0]), "r"(b[1]));
}

// ==================== tf32 mma.sync GEMM, cp.async 3-stage, 2 CTAs/SM ====================
// C[M,N] = A[M,K] @ B[K,N] (+bias, optional leaky). Any K%4==0 (zero-fill tail), N%4==0.
// 256 threads = 8 warps arranged WMW x (8/WMW); warp tile fixed 32x32.
// Shape A (K2):     BM=64,  BN=128, WMW=2  -> grid (N/128, M/64)
// Shape B (N=200):  BM=128, BN=64,  WMW=4  -> grid (N/64,  M/128)
template<int BM, int BN, int WMW, bool LEAKY_C>
__global__ __launch_bounds__(256, 2)
void mma_gemm(const float* __restrict__ A, int lda,
              const float* __restrict__ B, int ldb,
              const float* __restrict__ bias,
              float* __restrict__ C, int ldc,
              int M, int N, int K)
{
    constexpr int AST = 36;              // A smem row stride (words)
    constexpr int BST = BN + 8;          // B smem row stride (words)
    constexpr int A_WORDS = BM * AST;
    constexpr int STW = A_WORDS + 32 * BST;
    constexpr int STB = STW * 4;
    constexpr int A_PASS = BM / 32;
    constexpr int B_TPR  = BN / 4;       // threads per B row
    constexpr int B_RPP  = 256 / B_TPR;  // B rows per pass
    constexpr int B_PASS = 32 / B_RPP;

    extern __shared__ uint32_t sm[];

    const int tid = threadIdx.x;
    const int bm = blockIdx.y * BM;
    const int bn = blockIdx.x * BN;

    const int a_r = tid >> 3;            // 0..31
    const int a_c = (tid & 7) * 4;       // 0..28
    const int b_r = tid / B_TPR;
    const int b_c = (tid % B_TPR) * 4;

    const int lane = tid & 31;
    const int g  = lane >> 2;
    const int tg = lane & 3;
    const int w  = tid >> 5;
    const int wm = (w % WMW) * 32;
    const int wn = (w / WMW) * 32;

    const uint32_t smb = smem_u32(sm);
    const int NCH = (K + 31) >> 5;

    auto issue = [&](int chunk, int stage) {
        const int k0 = chunk * 32;
        const uint32_t ab = smb + stage * STB;
        const uint32_t bb = ab + A_WORDS * 4;
        #pragma unroll
        for (int i = 0; i < A_PASS; i++) {
            const int r = bm + a_r + 32 * i;
            const int col = k0 + a_c;
            const int ok = (r < M && col < K);
            const int rr = (r < M) ? r : 0;
            const int cc = (col < K) ? col : 0;
            cp_async16(ab + (a_r + 32 * i) * (AST * 4) + a_c * 4,
                       A + (size_t)rr * lda + cc, ok ? 16 : 0);
        }
        #pragma unroll
        for (int i = 0; i < B_PASS; i++) {
            const int r = k0 + b_r + B_RPP * i;
            const int c = bn + b_c;
            const int ok = (r < K && c < N);
            const int rr = (r < K) ? r : 0;
            const int cc = (c < N) ? c : 0;
            cp_async16(bb + (b_r + B_RPP * i) * (BST * 4) + b_c * 4,
                       B + (size_t)rr * ldb + cc, ok ? 16 : 0);
        }
    };

    #pragma unroll
    for (int s = 0; s < 3; s++) {
        if (s < NCH) issue(s, s);
        CP_COMMIT();
    }

    float acc[2][4][4];
    #pragma unroll
    for (int mi = 0; mi < 2; mi++)
        #pragma unroll
        for (int ni = 0; ni < 4; ni++)
            #pragma unroll
            for (int j = 0; j < 4; j++) acc[mi][ni][j] = 0.0f;

    int st = 0;
    for (int i = 0; i < NCH; i++) {
        CP_WAIT(2);
        __syncthreads();

        const uint32_t* As = sm + st * STW;
        const uint32_t* Bs = As + A_WORDS;

        #pragma unroll
        for (int k8 = 0; k8 < 32; k8 += 8) {
            uint32_t af[2][4], bf[4][2];
            #pragma unroll
            for (int mi = 0; mi < 2; mi++) {
                const int r = wm + mi * 16 + g;
                af[mi][0] = As[(r    ) * AST + k8 + tg];
                af[mi][1] = As[(r + 8) * AST + k8 + tg];
                af[mi][2] = As[(r    ) * AST + k8 + tg + 4];
                af[mi][3] = As[(r + 8) * AST + k8 + tg + 4];
            }
            #pragma unroll
            for (int ni = 0; ni < 4; ni++) {
                const int cn = wn + ni * 8 + g;
                bf[ni][0] = Bs[(k8 + tg    ) * BST + cn];
                bf[ni][1] = Bs[(k8 + tg + 4) * BST + cn];
            }
            #pragma unroll
            for (int mi = 0; mi < 2; mi++)
                #pragma unroll
                for (int ni = 0; ni < 4; ni++)
                    mma_tf32(acc[mi][ni], af[mi], bf[ni]);
        }
        __syncthreads();

        if (i + 3 < NCH) issue(i + 3, st);
        CP_COMMIT();

        st = (st == 2) ? 0 : st + 1;
    }

    // epilogue
    #pragma unroll
    for (int mi = 0; mi < 2; mi++) {
        #pragma unroll
        for (int ni = 0; ni < 4; ni++) {
            const int cn = bn + wn + ni * 8 + tg * 2;
            if (cn >= N) continue;
            const int r0 = bm + wm + mi * 16 + g;
            const int r1 = r0 + 8;
            const float bx = bias ? bias[cn]     : 0.f;
            const float by = bias ? bias[cn + 1] : 0.f;
            if (r0 < M) {
                float vx = acc[mi][ni][0] + bx;
                float vy = acc[mi][ni][1] + by;
                if (LEAKY_C) { vx = leakyf(vx); vy = leakyf(vy); }
                *(float2*)(C + (size_t)r0 * ldc + cn) = make_float2(vx, vy);
            }
            if (r1 < M) {
                float vx = acc[mi][ni][2] + bx;
                float vy = acc[mi][ni][3] + by;
                if (LEAKY_C) { vx = leakyf(vx); vy = leakyf(vy); }
                *(float2*)(C + (size_t)r1 * ldc + cn) = make_float2(vx, vy);
            }
        }
    }
}

#define GDYN_A (3 * ((64 * 36 + 32 * 136) * 4))    // 79872
#define GDYN_B (3 * ((128 * 36 + 32 * 72) * 4))    // 82944

// ---------------- drug branch ----------------
__global__ void drug_kernel(const float* __restrict__ drug_feature,
                            const float* __restrict__ drug_mol_feature,
                            const float* __restrict__ hpo_drug_W, const float* __restrict__ hpo_drug_b,
                            const float* __restrict__ md_W1, const float* __restrict__ md_b1,
                            const float* __restrict__ md_W2, const float* __restrict__ md_b2,
                            const float* __restrict__ dl1_W, const float* __restrict__ dl1_b,
                            const float* __restrict__ dl2_W, const float* __restrict__ dl2_b)
{
    __shared__ float s_feat[1024];
    __shared__ float s_mol [1024];
    __shared__ float s_t   [256];
    __shared__ float s_d1  [400];
    __shared__ float s_d2  [200];

    const int row = blockIdx.x;
    const int tid = threadIdx.x;

    for (int k = tid; k < 1024; k += 256) {
        s_feat[k] = drug_feature[row * 1024 + k];
        s_mol [k] = drug_mol_feature[row * 1024 + k];
    }
    __syncthreads();

    {
        float acc = md_b1[tid];
        for (int k = 0; k < 1024; k++) acc = fmaf(s_mol[k], md_W1[k * 256 + tid], acc);
        s_t[tid] = leakyf(acc);
    }
    __syncthreads();

    if (tid < 200) {
        float acc = md_b2[tid];
        for (int k = 0; k < 256; k++) acc = fmaf(s_t[k], md_W2[k * 200 + tid], acc);
        s_d1[tid] = leakyf(acc);
        float acc2 = hpo_drug_b[tid];
        for (int k = 0; k < 1024; k++) acc2 = fmaf(s_feat[k], hpo_drug_W[k * 200 + tid], acc2);
        s_d1[200 + tid] = leakyf(acc2);
    }
    __syncthreads();

    if (tid < 200) {
        float acc = dl1_b[tid];
        for (int k = 0; k < 400; k++) acc = fmaf(s_d1[k], dl1_W[k * 200 + tid], acc);
        s_d2[tid] = leakyf(acc);
    }
    __syncthreads();

    if (tid < 200) {
        float acc = dl2_b[tid];
        for (int k = 0; k < 200; k++) acc = fmaf(s_d2[k], dl2_W[k * 200 + tid], acc);
        g_d[row * 200 + tid] = acc;
    }
}

// ---------------- graph preprocessing ----------------
__global__ void zero_cnt_kernel() {
    int i = blockIdx.x * blockDim.x + threadIdx.x;
    if (i < N_NODES) g_cnt[i] = 0;
}

__global__ void count_deg_kernel(const int* __restrict__ dst) {
    int i = blockIdx.x * blockDim.x + threadIdx.x;
    if (i < NE) atomicAdd(&g_cnt[dst[i]], 1);
}

// fused dinv + exclusive scan (warp-shuffle based), single block of 1024
__global__ void scan_kernel() {
    __shared__ int warp_sums[32];
    const int t = threadIdx.x;
    const int lane = t & 31;
    const int wid = t >> 5;
    const int lo = t * 8;

    int cnt[8];
    int sum = 0;
    #pragma unroll
    for (int j = 0; j < 8; j++) {
        const int i = lo + j;
        const int c = (i < N_NODES) ? g_cnt[i] : 0;
        cnt[j] = c;
        sum += c;
        if (i < N_NODES) g_dinv[i] = rsqrtf((float)c + 2.0f);
    }

    int inc = sum;
    #pragma unroll
    for (int o = 1; o < 32; o <<= 1) {
        int v = __shfl_up_sync(0xffffffff, inc, o);
        if (lane >= o) inc += v;
    }
    if (lane == 31) warp_sums[wid] = inc;
    __syncthreads();
    if (wid == 0) {
        int v = warp_sums[lane];
        int s = v;
        #pragma unroll
        for (int o = 1; o < 32; o <<= 1) {
            int u = __shfl_up_sync(0xffffffff, s, o);
            if (lane >= o) s += u;
        }
        warp_sums[lane] = s - v;  // exclusive
    }
    __syncthreads();

    int run = warp_sums[wid] + inc - sum;
    #pragma unroll
    for (int j = 0; j < 8; j++) {
        const int i = lo + j;
        if (i < N_NODES) {
            g_rowstart[i] = run;
            g_cursor[i]   = run;
            run += cnt[j];
        }
    }
    if (t == 0) g_rowstart[N_NODES] = NE;
}

__global__ void csr_fill_kernel(const int* __restrict__ src, const int* __restrict__ dst) {
    int i = blockIdx.x * blockDim.x + threadIdx.x;
    if (i < NE) {
        int p = atomicAdd(&g_cursor[dst[i]], 1);
        g_csrc[p] = src[i];
    }
}

// ---------------- GCN aggregation ----------------
__global__ void gcn_aggregate_kernel(const float* __restrict__ h,
                                     const float* __restrict__ bias,
                                     float* __restrict__ out)
{
    const int node = blockIdx.x;
    const int t = threadIdx.x;
    const int c = t * 4;
    const bool act = c < DDIM;

    const float di = g_dinv[node];
    const int e0 = g_rowstart[node];
    const int e1 = g_rowstart[node + 1];

    float ax = 0.f, ay = 0.f, az = 0.f, aw = 0.f;
    for (int e = e0; e < e1; e++) {
        const int s = g_csrc[e];
        const float w = di * g_dinv[s];
        if (act) {
            const float4 hv = *(const float4*)(h + (size_t)s * DDIM + c);
            ax = fmaf(w, hv.x, ax);
            ay = fmaf(w, hv.y, ay);
            az = fmaf(w, hv.z, az);
            aw = fmaf(w, hv.w, aw);
        }
    }
    if (act) {
        const float sw = 2.0f * di * di;
        const float4 hv = *(const float4*)(h + (size_t)node * DDIM + c);
        const float4 bv = *(const float4*)(bias + c);
        float4 o;
        o.x = fmaf(sw, hv.x, ax) + bv.x;
        o.y = fmaf(sw, hv.y, ay) + bv.y;
        o.z = fmaf(sw, hv.z, az) + bv.z;
        o.w = fmaf(sw, hv.w, aw) + bv.w;
        *(float4*)(out + (size_t)node * DDIM + c) = o;
    }
}

// ---------------- cosine + sigmoid ----------------
__global__ void cosine_kernel(float* __restrict__ out) {
    const int gwarp = (blockIdx.x * blockDim.x + threadIdx.x) >> 5;
    const int lane = threadIdx.x & 31;
    if (gwarp >= N_NODES) return;

    const int b = gwarp / NPROT;
    const float* dv = g_d + b * DDIM;
    const float* pv = g_a2 + (size_t)gwarp * DDIM;

    float dot = 0.f, dd = 0.f, pp = 0.f;
    for (int c = lane; c < DDIM; c += 32) {
        const float x = dv[c], y = pv[c];
        dot = fmaf(x, y, dot);
        dd  = fmaf(x, x, dd);
        pp  = fmaf(y, y, pp);
    }
    #pragma unroll
    for (int o = 16; o > 0; o >>= 1) {
        dot += __shfl_down_sync(0xffffffff, dot, o);
        dd  += __shfl_down_sync(0xffffffff, dd, o);
        pp  += __shfl_down_sync(0xffffffff, pp, o);
    }
    if (lane == 0) {
        const float den = fmaxf(sqrtf(dd), 1e-8f) * fmaxf(sqrtf(pp), 1e-8f);
        out[gwarp] = 1.0f / (1.0f + expf(-dot / den));
    }
}

// ---------------- launch ----------------
extern "C" void kernel_launch(void* const* d_in, const int* in_sizes, int n_in,
                              void* d_out, int out_size)
{
    (void)in_sizes; (void)n_in; (void)out_size;

    const float* PPI_x      = (const float*)d_in[0];
    const float* PMF        = (const float*)d_in[1];
    const float* drug_feat  = (const float*)d_in[2];
    const float* drug_mol   = (const float*)d_in[3];
    const int*   edge_index = (const int*)  d_in[4];
    const float* hpo_drug_W = (const float*)d_in[5];
    const float* hpo_drug_b = (const float*)d_in[6];
    const float* hpo_prot_W = (const float*)d_in[7];
    const float* hpo_prot_b = (const float*)d_in[8];
    const float* mp_W1 = (const float*)d_in[9];
    const float* mp_b1 = (const float*)d_in[10];
    const float* mp_W2 = (const float*)d_in[11];
    const float* mp_b2 = (const float*)d_in[12];
    const float* md_W1 = (const float*)d_in[13];
    const float* md_b1 = (const float*)d_in[14];
    const float* md_W2 = (const float*)d_in[15];
    const float* md_b2 = (const float*)d_in[16];
    const float* pl1_W = (const float*)d_in[17];
    const float* pl1_b = (const float*)d_in[18];
    const float* dl1_W = (const float*)d_in[19];
    const float* dl1_b = (const float*)d_in[20];
    const float* dl2_W = (const float*)d_in[21];
    const float* dl2_b = (const float*)d_in[22];
    const float* g1_W  = (const float*)d_in[23];
    const float* g1_b  = (const float*)d_in[24];
    const float* g2_W  = (const float*)d_in[25];
    const float* g2_b  = (const float*)d_in[26];

    const int* e_src = edge_index;
    const int* e_dst = edge_index + NE;

    float *p_cat, *p_t, *p_px2, *p_h, *p_a1, *p_a2;
    cudaGetSymbolAddress((void**)&p_cat,  g_cat);
    cudaGetSymbolAddress((void**)&p_t,    g_t);
    cudaGetSymbolAddress((void**)&p_px2,  g_px2);
    cudaGetSymbolAddress((void**)&p_h,    g_h);
    cudaGetSymbolAddress((void**)&p_a1,   g_a1);
    cudaGetSymbolAddress((void**)&p_a2,   g_a2);

    float* out = (float*)d_out;

    cudaFuncSetAttribute((const void*)mma_gemm<64, 128, 2, true>,
                         cudaFuncAttributeMaxDynamicSharedMemorySize, GDYN_A);
    cudaFuncSetAttribute((const void*)mma_gemm<128, 64, 4, true>,
                         cudaFuncAttributeMaxDynamicSharedMemorySize, GDYN_B);
    cudaFuncSetAttribute((const void*)mma_gemm<128, 64, 4, false>,
                         cudaFuncAttributeMaxDynamicSharedMemorySize, GDYN_B);

    dim3 blk(256);

    // 0: drug branch
    drug_kernel<<<NBATCH, 256>>>(drug_feat, drug_mol,
                                 hpo_drug_W, hpo_drug_b,
                                 md_W1, md_b1, md_W2, md_b2,
                                 dl1_W, dl1_b, dl2_W, dl2_b);
    // 1,2: preprocessing
    zero_cnt_kernel<<<(N_NODES + 255) / 256, 256>>>();
    count_deg_kernel<<<(NE + 255) / 256, 256>>>(e_dst);
    // 3: K2 (big GEMM; kept at launch idx 3 for ncu)
    mma_gemm<64, 128, 2, true><<<dim3(2, 125), blk, GDYN_A>>>(
        PMF, 8192, mp_W1, 256, mp_b1, p_t, 256, N_NODES, 256, 8192);
    // 4,5: rest of preprocessing
    scan_kernel<<<1, 1024>>>();
    csr_fill_kernel<<<(NE + 255) / 256, 256>>>(e_src, e_dst);
    // 6: K1 -> leaky(px) -> g_cat[:, 0:200]
    mma_gemm<128, 64, 4, true><<<dim3(4, 63), blk, GDYN_B>>>(
        PPI_x, 1024, hpo_prot_W, 200, hpo_prot_b, p_cat, 400, N_NODES, 200, 1024);
    // 7: K3 -> leaky(pm) -> g_cat[:, 200:400]
    mma_gemm<128, 64, 4, true><<<dim3(4, 63), blk, GDYN_B>>>(
        p_t, 256, mp_W2, 200, mp_b2, p_cat + 200, 400, N_NODES, 200, 256);
    // 8: K4: px2 = cat @ pl1_W + b
    mma_gemm<128, 64, 4, false><<<dim3(4, 63), blk, GDYN_B>>>(
        p_cat, 400, pl1_W, 200, pl1_b, p_px2, 200, N_NODES, 200, 400);
    // 9,10: GCN layer 1
    mma_gemm<128, 64, 4, false><<<dim3(4, 63), blk, GDYN_B>>>(
        p_px2, 200, g1_W, 200, (const float*)nullptr, p_h, 200, N_NODES, 200, 200);
    gcn_aggregate_kernel<<<N_NODES, 64>>>(p_h, g1_b, p_a1);
    // 11,12: GCN layer 2
    mma_gemm<128, 64, 4, false><<<dim3(4, 63), blk, GDYN_B>>>(
        p_a1, 200, g2_W, 200, (const float*)nullptr, p_h, 200, N_NODES, 200, 200);
    gcn_aggregate_kernel<<<N_NODES, 64>>>(p_h, g2_b, p_a2);
    // 13: cosine + sigmoid
    cosine_kernel<<<(N_NODES * 32 + 255) / 256, 256>>>(out);
}